// round 11
// baseline (speedup 1.0000x reference)
#include <cuda_runtime.h>
#include <cstdint>

#define T_TOKENS 16384
#define DIMX     2048
#define NE       8
#define KSEL     2048

// libdevice exp — exact bits, immune to fast-math flags.
extern "C" __device__ float __nv_expf(float);

// W lives in the 64KB constant bank: reads are warp-uniform -> LDC on the
// dedicated constant port, completely off the shared-memory crossbar.
__constant__ float4 c_W4[NE * DIMX / 4];   // exactly 65536 bytes

// Scratch: per-expert sort keys (key = ~bits(sigmoid(logit))) and a global
// 14-bit histogram of keys per expert (level 0 of the radix select).
// g_hist is zero at module load and re-zeroed by k2 every call (replay-safe).
__device__ unsigned int g_keys[NE * T_TOKENS];
__device__ unsigned int g_hist[NE * 16384];

// ---------------------------------------------------------------------------
// Kernel 1: logits + keys + global key-histogram.
// Block = 64-token tile, 8 warps. Warp w: expert-pair P = w&3, token subgroup
// S = w>>2. Thread = 1 token x 2 experts: two independent in-order scalar
// fma.rn chains over ascending dims (bitwise identical to all passing rounds).
// Per 4-dim group: 1 x-LDS.128 (32 distinct tokens -> crossbar-optimal)
// + 2 LDC.128 (constant port) + 8 FMA. 2048 warps = 3.46/SMSP hides latency.
// ---------------------------------------------------------------------------
#define K1T   256
#define TILE  64
#define CH    32
#define XP    36      // x pitch: 144B rows, conflict-free LDS.128

__global__ void __launch_bounds__(K1T) k1_gemv(const float* __restrict__ x)
{
    __shared__ float sx[2][TILE * XP];   // 18.4 KB double buffer

    const int tid  = threadIdx.x;
    const int lane = tid & 31;
    const int w    = tid >> 5;
    const int P    = w & 3;          // expert pair: experts 2P, 2P+1
    const int S    = w >> 2;         // token subgroup (0/1)
    const int tloc = S * 32 + lane;  // token within tile
    const size_t rowBase = (size_t)blockIdx.x * TILE;

    // Staging: 64 rows x 8 float4-cols per 32-dim chunk = 512 float4; 2/thread.
    const int r0 = tid >> 3,            c0 = tid & 7;
    const int r1 = (tid + K1T) >> 3,    c1 = (tid + K1T) & 7;

    const float* xb = x + rowBase * DIMX;

    float4 pf0, pf1;
    pf0 = *reinterpret_cast<const float4*>(xb + (size_t)r0 * DIMX + c0 * 4);
    pf1 = *reinterpret_cast<const float4*>(xb + (size_t)r1 * DIMX + c1 * 4);
    *reinterpret_cast<float4*>(&sx[0][r0 * XP + c0 * 4]) = pf0;
    *reinterpret_cast<float4*>(&sx[0][r1 * XP + c1 * 4]) = pf1;
    pf0 = *reinterpret_cast<const float4*>(xb + (size_t)r0 * DIMX + CH + c0 * 4);
    pf1 = *reinterpret_cast<const float4*>(xb + (size_t)r1 * DIMX + CH + c1 * 4);

    float a0 = 0.0f, a1 = 0.0f;

    __syncthreads();   // buf0 staged

    const int wrow0 = (2 * P) * (DIMX / 4);       // float4 row offsets in c_W4
    const int wrow1 = (2 * P + 1) * (DIMX / 4);

    for (int ch = 0; ch < DIMX / CH; ++ch) {
        const int cur = ch & 1;

        if (ch + 1 < DIMX / CH) {                 // stage chunk ch+1
            *reinterpret_cast<float4*>(&sx[cur ^ 1][r0 * XP + c0 * 4]) = pf0;
            *reinterpret_cast<float4*>(&sx[cur ^ 1][r1 * XP + c1 * 4]) = pf1;
        }
        if (ch + 2 < DIMX / CH) {                 // prefetch chunk ch+2
            const float* xc = xb + (ch + 2) * CH;
            pf0 = *reinterpret_cast<const float4*>(xc + (size_t)r0 * DIMX + c0 * 4);
            pf1 = *reinterpret_cast<const float4*>(xc + (size_t)r1 * DIMX + c1 * 4);
        }

        const float* xd = &sx[cur][tloc * XP];
#pragma unroll
        for (int g = 0; g < CH / 4; ++g) {
            float4 xv = *reinterpret_cast<const float4*>(xd + g * 4);
            float4 k0 = c_W4[wrow0 + ch * (CH / 4) + g];   // LDC.128, uniform
            float4 k1 = c_W4[wrow1 + ch * (CH / 4) + g];   // LDC.128, uniform
            a0 = __fmaf_rn(xv.x, k0.x, a0);  a1 = __fmaf_rn(xv.x, k1.x, a1);
            a0 = __fmaf_rn(xv.y, k0.y, a0);  a1 = __fmaf_rn(xv.y, k1.y, a1);
            a0 = __fmaf_rn(xv.z, k0.z, a0);  a1 = __fmaf_rn(xv.z, k1.z, a1);
            a0 = __fmaf_rn(xv.w, k0.w, a0);  a1 = __fmaf_rn(xv.w, k1.w, a1);
        }
        __syncthreads();
    }

    // sigmoid (exp form, bit-matched) -> monotone descending key; emit 2.
    const int token = (int)rowBase + tloc;
    float accs[2] = {a0, a1};
#pragma unroll
    for (int u = 0; u < 2; ++u) {
        int e = 2 * P + u;
        float em = __nv_expf(-accs[u]);
        float s  = __fdiv_rn(1.0f, __fadd_rn(1.0f, em));
        unsigned key = ~__float_as_uint(s);
        g_keys[e * T_TOKENS + token] = key;
        unsigned h = (unsigned)e * 16384u + (key >> 18);
        unsigned m = __match_any_sync(0xffffffffu, h);
        if ((int)lane == __ffs(m) - 1)
            atomicAdd(&g_hist[h], (unsigned)__popc(m));
    }
}

// ---------------------------------------------------------------------------
// Kernel 2: per-expert exact top-2048 (desc, ties -> lower index).
// (unchanged from R10 — passing at 27.6us)
// ---------------------------------------------------------------------------
#define K2_THREADS 1024
#define HC         4
#define MASK46     ((1ull << 46) - 1)

__global__ void __launch_bounds__(K2_THREADS) k2_topk(float* __restrict__ out, int writeIdx)
{
    extern __shared__ unsigned char sm2[];
    unsigned int*        hist  = reinterpret_cast<unsigned int*>(sm2);
    unsigned int*        hscan = reinterpret_cast<unsigned int*>(sm2 + 65536);
    unsigned long long*  sel   = reinterpret_cast<unsigned long long*>(sm2 + 81920);
    unsigned long long*  cand  = reinterpret_cast<unsigned long long*>(sm2 + 98304);

    __shared__ unsigned int s_wsum[32];
    __shared__ unsigned long long s_pref;
    __shared__ unsigned long long s_mask;
    __shared__ unsigned long long s_kstar;
    __shared__ int          s_want;
    __shared__ int          s_bin;
    __shared__ unsigned int s_before;
    __shared__ int          s_exact;
    __shared__ int          s_n;

    const int e    = blockIdx.x;
    const int tid  = threadIdx.x;
    const unsigned lane = tid & 31;
    const int wid  = tid >> 5;

    unsigned kreg[16];
    {
        const unsigned* gk = g_keys + e * T_TOKENS;
#pragma unroll
        for (int r = 0; r < 16; ++r)
            kreg[r] = gk[tid + r * K2_THREADS];
    }

    if (tid == 0) { s_exact = 0; s_n = 0; }
    __syncthreads();

    // ---- Level 0: scan global 14-bit histogram (16 bins/thread) ----
    {
        const uint4* gh = reinterpret_cast<const uint4*>(g_hist + e * 16384);
        unsigned lsum = 0;
        uint4 u0 = gh[tid * 4 + 0], u1 = gh[tid * 4 + 1];
        uint4 u2 = gh[tid * 4 + 2], u3 = gh[tid * 4 + 3];
        lsum = u0.x + u0.y + u0.z + u0.w + u1.x + u1.y + u1.z + u1.w
             + u2.x + u2.y + u2.z + u2.w + u3.x + u3.y + u3.z + u3.w;
        unsigned si = lsum;
#pragma unroll
        for (int o = 1; o < 32; o <<= 1) {
            unsigned n = __shfl_up_sync(0xffffffffu, si, o);
            if (lane >= (unsigned)o) si += n;
        }
        if (lane == 31) s_wsum[wid] = si;
        __syncthreads();
        if (wid == 0) {
            unsigned w = s_wsum[lane];
            unsigned wi = w;
#pragma unroll
            for (int o = 1; o < 32; o <<= 1) {
                unsigned n = __shfl_up_sync(0xffffffffu, wi, o);
                if (lane >= (unsigned)o) wi += n;
            }
            s_wsum[lane] = wi - w;
        }
        __syncthreads();
        unsigned base = s_wsum[wid] + (si - lsum);
        if ((int)base < KSEL && (int)(base + lsum) >= KSEL) {
            const unsigned* gb = g_hist + e * 16384 + tid * 16;
            unsigned run = base;
            for (int j = 0; j < 16; ++j) {
                unsigned c = gb[j];
                if ((int)run < KSEL && (int)(run + c) >= KSEL) {
                    s_bin = tid * 16 + j;
                    s_before = run;
                    if ((int)(run + c) == KSEL) s_exact = 1;
                    break;
                }
                run += c;
            }
        }
        __syncthreads();
        if (tid == 0) {
            s_want = KSEL - (int)s_before;
            s_pref = (unsigned long long)(unsigned)s_bin << 32;
            s_mask = 0x3FFFull << 32;
        }
        __syncthreads();
    }

    unsigned long long Kstar;
    if (s_exact) {
        Kstar = s_pref | 0xFFFFFFFFull;
    } else {
        const unsigned binv = (unsigned)s_bin;
#pragma unroll
        for (int r = 0; r < 16; ++r) {
            bool c = ((kreg[r] >> 18) == binv);
            unsigned bal = __ballot_sync(0xffffffffu, c);
            int base = 0;
            if (lane == 0 && bal) base = atomicAdd(&s_n, __popc(bal));
            base = __shfl_sync(0xffffffffu, base, 0);
            if (c) {
                int pos = base + __popc(bal & ((1u << lane) - 1u));
                if (pos < 2048)
                    cand[pos] = ((unsigned long long)kreg[r] << 14)
                              | (unsigned)(tid + r * K2_THREADS);
            }
        }
        __syncthreads();
        const int m = s_n;
        const int want = s_want;

        if (m <= 64) {
            if (wid == 0) {
                unsigned long long a = (lane < (unsigned)m) ? cand[lane] : ~0ull;
                unsigned long long b = (lane + 32 < (unsigned)m) ? cand[lane + 32] : ~0ull;
                const int g0 = (int)lane, g1 = (int)lane + 32;
                for (int k = 2; k <= 64; k <<= 1) {
                    for (int j = k >> 1; j >= 1; j >>= 1) {
                        if (j == 32) {
                            bool asc = ((g0 & k) == 0);
                            if ((a > b) == asc) { unsigned long long t = a; a = b; b = t; }
                        } else {
                            unsigned long long pa = __shfl_xor_sync(0xffffffffu, a, j);
                            unsigned long long pb = __shfl_xor_sync(0xffffffffu, b, j);
                            bool lower = ((lane & (unsigned)j) == 0u);
                            bool ascA  = ((g0 & k) == 0);
                            bool ascB  = ((g1 & k) == 0);
                            unsigned long long amin = (a < pa) ? a : pa;
                            unsigned long long amax = (a < pa) ? pa : a;
                            unsigned long long bmin = (b < pb) ? b : pb;
                            unsigned long long bmax = (b < pb) ? pb : b;
                            a = (lower == ascA) ? amin : amax;
                            b = (lower == ascB) ? bmin : bmax;
                        }
                    }
                }
                int idx = want - 1;
                unsigned long long va = __shfl_sync(0xffffffffu, a, idx & 31);
                unsigned long long vb = __shfl_sync(0xffffffffu, b, idx & 31);
                if (lane == 0) s_kstar = (idx < 32) ? va : vb;
            }
            __syncthreads();
            Kstar = s_kstar;
        } else {
            const int shifts[3] = {20, 10, 0};
            const int nbits [3] = {12, 10, 10};
            for (int lvl = 0; lvl < 3; ++lvl) {
                const int shift = shifts[lvl];
                const int nb    = 1 << nbits[lvl];
                const int wantLoc              = s_want;
                const unsigned long long mask  = s_mask;
                const unsigned long long pref  = s_pref;

                for (int i = tid; i < HC * 4096; i += K2_THREADS) hist[i] = 0u;
                __syncthreads();

                unsigned int* myhist = hist + (wid & (HC - 1)) * 4096;
#pragma unroll
                for (int r = 0; r < 16; ++r) {
                    unsigned long long K = ((unsigned long long)kreg[r] << 14)
                                         | (unsigned)(tid + r * K2_THREADS);
                    bool mm = ((K & mask) == pref);
                    unsigned active = __ballot_sync(0xffffffffu, mm);
                    if (mm) {
                        int bin = (int)((K >> shift) & (unsigned)(nb - 1));
                        unsigned same = __match_any_sync(active, bin);
                        if ((int)lane == (__ffs(same) - 1))
                            atomicAdd(&myhist[bin], (unsigned)__popc(same));
                    }
                }
                __syncthreads();
                {
                    unsigned v[4];
                    unsigned sthr = 0;
#pragma unroll
                    for (int j = 0; j < 4; ++j) {
                        int b = 4 * tid + j;
                        unsigned t = 0;
#pragma unroll
                        for (int c = 0; c < HC; ++c) t += hist[c * 4096 + b];
                        v[j] = t; sthr += t;
                    }
                    unsigned si = sthr;
#pragma unroll
                    for (int o = 1; o < 32; o <<= 1) {
                        unsigned n = __shfl_up_sync(0xffffffffu, si, o);
                        if (lane >= (unsigned)o) si += n;
                    }
                    if (lane == 31) s_wsum[wid] = si;
                    __syncthreads();
                    if (wid == 0) {
                        unsigned w = s_wsum[lane];
                        unsigned wi = w;
#pragma unroll
                        for (int o = 1; o < 32; o <<= 1) {
                            unsigned n = __shfl_up_sync(0xffffffffu, wi, o);
                            if (lane >= (unsigned)o) wi += n;
                        }
                        s_wsum[lane] = wi - w;
                    }
                    __syncthreads();
                    unsigned run = s_wsum[wid] + (si - sthr);
#pragma unroll
                    for (int j = 0; j < 4; ++j) {
                        run += v[j];
                        hscan[4 * tid + j] = run;
                    }
                }
                __syncthreads();
                for (int i = tid; i < nb; i += K2_THREADS) {
                    unsigned c = hscan[i];
                    unsigned p = (i > 0) ? hscan[i - 1] : 0u;
                    if ((int)c >= wantLoc && (int)p < wantLoc) {
                        s_bin = i; s_before = p;
                        if ((int)c == wantLoc) s_exact = 1;
                    }
                }
                __syncthreads();
                if (tid == 0) {
                    s_want = wantLoc - (int)s_before;
                    s_pref = pref | ((unsigned long long)(unsigned)s_bin << shift);
                    s_mask = mask | ((unsigned long long)(unsigned)(nb - 1) << shift);
                }
                __syncthreads();
                if (s_exact) break;
            }
            Kstar = s_pref | (~s_mask & MASK46);
        }
    }

    // ---- Final collect (atomic-free two-pass) ----
    {
        int cw = 0;
#pragma unroll
        for (int r = 0; r < 16; ++r) {
            unsigned long long K = ((unsigned long long)kreg[r] << 14)
                                 | (unsigned)(tid + r * K2_THREADS);
            unsigned bal = __ballot_sync(0xffffffffu, K <= Kstar);
            cw += __popc(bal);
        }
        if (lane == 0) s_wsum[wid] = (unsigned)cw;
        __syncthreads();
        if (wid == 0) {
            unsigned w = s_wsum[lane];
            unsigned wi = w;
#pragma unroll
            for (int o = 1; o < 32; o <<= 1) {
                unsigned n = __shfl_up_sync(0xffffffffu, wi, o);
                if (lane >= (unsigned)o) wi += n;
            }
            s_wsum[lane] = wi - w;
        }
        __syncthreads();
        int base = (int)s_wsum[wid];
#pragma unroll
        for (int r = 0; r < 16; ++r) {
            unsigned long long K = ((unsigned long long)kreg[r] << 14)
                                 | (unsigned)(tid + r * K2_THREADS);
            bool take = (K <= Kstar);
            unsigned bal = __ballot_sync(0xffffffffu, take);
            if (take) {
                int pos = base + __popc(bal & ((1u << lane) - 1u));
                sel[pos] = K;
            }
            base += __popc(bal);
        }
    }
    __syncthreads();

    // ---- Hybrid bitonic sort ascending over sel[2048] ----
    const int g0 = (wid << 6) | (int)lane;
    const int g1 = g0 + 32;
    unsigned long long a = sel[g0];
    unsigned long long b = sel[g1];

    for (int k = 2; k <= KSEL; k <<= 1) {
        int j = k >> 1;
        if (j >= 64) {
            sel[g0] = a; sel[g1] = b;
            __syncthreads();
            for (; j >= 64; j >>= 1) {
                int i = ((tid & ~(j - 1)) << 1) | (tid & (j - 1));
                int l = i | j;
                unsigned long long u = sel[i];
                unsigned long long v = sel[l];
                bool asc = ((i & k) == 0);
                if ((u > v) == asc) { sel[i] = v; sel[l] = u; }
                __syncthreads();
            }
            a = sel[g0]; b = sel[g1];
        }
        for (; j >= 1; j >>= 1) {
            if (j == 32) {
                bool asc = ((g0 & k) == 0);
                if ((a > b) == asc) { unsigned long long t = a; a = b; b = t; }
            } else {
                unsigned long long pa = __shfl_xor_sync(0xffffffffu, a, j);
                unsigned long long pb = __shfl_xor_sync(0xffffffffu, b, j);
                bool lower = ((lane & (unsigned)j) == 0u);
                bool ascA  = ((g0 & k) == 0);
                bool ascB  = ((g1 & k) == 0);
                unsigned long long amin = (a < pa) ? a : pa;
                unsigned long long amax = (a < pa) ? pa : a;
                unsigned long long bmin = (b < pb) ? b : pb;
                unsigned long long bmax = (b < pb) ? pb : b;
                a = (lower == ascA) ? amin : amax;
                b = (lower == ascB) ? bmin : bmax;
            }
        }
    }

    // Re-zero this expert's g_hist slice (restores invariant for replay).
    {
        uint4 z = make_uint4(0u, 0u, 0u, 0u);
        uint4* gz = reinterpret_cast<uint4*>(g_hist + e * 16384);
        for (int i = tid; i < 16384 / 4; i += K2_THREADS) gz[i] = z;
    }

    {
        float scA = __uint_as_float(~(unsigned)(a >> 14));
        float scB = __uint_as_float(~(unsigned)(b >> 14));
        out[e * KSEL + g0] = scA;
        out[e * KSEL + g1] = scB;
        if (writeIdx) {
            out[NE * KSEL + e * KSEL + g0] = (float)(unsigned)(a & 0x3FFFu);
            out[NE * KSEL + e * KSEL + g1] = (float)(unsigned)(b & 0x3FFFu);
        }
    }
}

// ---------------------------------------------------------------------------
extern "C" void kernel_launch(void* const* d_in, const int* in_sizes, int n_in,
                              void* d_out, int out_size)
{
    const float* x = (const float*)d_in[0];   // [16384, 2048] f32
    const float* W = (const float*)d_in[1];   // [8, 2048] f32
    float* out = (float*)d_out;

    const int SMEM2 = 65536 + 16384 + 16384 + 16384;  // 114688
    cudaFuncSetAttribute(k2_topk, cudaFuncAttributeMaxDynamicSharedMemorySize, SMEM2);

    const int writeIdx = (out_size >= 2 * NE * KSEL) ? 1 : 0;

    // W -> constant bank (D2D memcpy node; graph-capturable).
    cudaMemcpyToSymbolAsync(c_W4, W, NE * DIMX * sizeof(float), 0,
                            cudaMemcpyDeviceToDevice);

    k1_gemv<<<T_TOKENS / TILE, K1T>>>(x);
    k2_topk<<<NE, K2_THREADS, SMEM2>>>(out, writeIdx);
}

// round 12
// speedup vs baseline: 3.7878x; 3.7878x over previous
#include <cuda_runtime.h>
#include <cstdint>

#define T_TOKENS 16384
#define DIMX     2048
#define NE       8
#define KSEL     2048

// libdevice exp — exact bits, immune to fast-math flags.
extern "C" __device__ float __nv_expf(float);

// Scratch: per-expert sort keys (key = ~bits(sigmoid(logit))) and a global
// 14-bit histogram of keys per expert (level 0 of the radix select).
// g_hist is zero at module load and re-zeroed by k2 every call (replay-safe).
__device__ unsigned int g_keys[NE * T_TOKENS];
__device__ unsigned int g_hist[NE * 16384];

// ---------------------------------------------------------------------------
// Kernel 1: logits + keys + global key-histogram.
// R9 structure (best measured): block = 64-token tile, 4 warps; warp P =
// expert pair (2P, 2P+1); lanes = tokens {lane, lane+32}. Thread: 4
// independent in-order scalar fma.rn chains — bitwise identical to all
// passing rounds. FIX vs R9: W packed as float4 expert-pair pairs
// ({e0 d, e1 d, e0 d+1, e1 d+1}) -> 2 broadcast LDS.128 per 4-dim group
// instead of 4 LDS.64: per-group shared ops 6 -> 4 (crossbar law: 4cyc/op).
// ---------------------------------------------------------------------------
#define K1T    128
#define TILE   64
#define CH     32
#define XP     36                 // 144B x rows: 16B aligned, 4-phase LDS.128
#define WPP    4100               // per-pair pitch: 512 groups * 8 floats + 4

__global__ void __launch_bounds__(K1T) k1_gemv(const float* __restrict__ x,
                                               const float* __restrict__ W)
{
    extern __shared__ float sm[];
    float* swp = sm;                         // [4][WPP]  packed pairs, 65.6KB
    float* sx  = sm + 4 * WPP;               // [2][TILE*XP] double buffer, 18.4KB

    const int tid  = threadIdx.x;
    const int lane = tid & 31;
    const int P    = tid >> 5;               // expert pair 0..3
    const int e0   = 2 * P, e1 = e0 + 1;
    const size_t rowBase = (size_t)blockIdx.x * TILE;

    // Stage W pair P: swp[P][d4*8 ..] = {e0 d0, e1 d0, e0 d1, e1 d1,
    //                                    e0 d2, e1 d2, e0 d3, e1 d3}
    {
        const float4* W0 = reinterpret_cast<const float4*>(W + e0 * DIMX);
        const float4* W1 = reinterpret_cast<const float4*>(W + e1 * DIMX);
        float* dst = swp + P * WPP;
#pragma unroll 4
        for (int it = 0; it < 16; ++it) {
            int d4 = it * 32 + lane;
            float4 w0 = W0[d4];
            float4 w1 = W1[d4];
            float4* dp = reinterpret_cast<float4*>(dst + d4 * 8);
            dp[0] = make_float4(w0.x, w1.x, w0.y, w1.y);
            dp[1] = make_float4(w0.z, w1.z, w0.w, w1.w);
        }
    }

    // x staging assignment: 64 rows x 8 float4-cols per 32-dim chunk.
    int rr[4], cc[4];
#pragma unroll
    for (int k = 0; k < 4; ++k) {
        int idx = tid + k * K1T;
        rr[k] = idx >> 3;
        cc[k] = idx & 7;
    }

    const float* xb = x + rowBase * DIMX;

    // Prologue: chunk 0 -> buf0; prefetch chunk 1.
    float4 pf[4];
#pragma unroll
    for (int k = 0; k < 4; ++k)
        pf[k] = *reinterpret_cast<const float4*>(xb + (size_t)rr[k] * DIMX + cc[k] * 4);
#pragma unroll
    for (int k = 0; k < 4; ++k)
        *reinterpret_cast<float4*>(&sx[rr[k] * XP + cc[k] * 4]) = pf[k];
#pragma unroll
    for (int k = 0; k < 4; ++k)
        pf[k] = *reinterpret_cast<const float4*>(xb + (size_t)rr[k] * DIMX + CH + cc[k] * 4);

    float a00 = 0.0f, a01 = 0.0f, a10 = 0.0f, a11 = 0.0f;

    __syncthreads();   // buf0 + swp staged

    const float* wb0 = swp + P * WPP;

    for (int ch = 0; ch < DIMX / CH; ++ch) {
        const int cur = ch & 1;

        if (ch + 1 < DIMX / CH) {             // stage chunk ch+1 into other buf
#pragma unroll
            for (int k = 0; k < 4; ++k)
                *reinterpret_cast<float4*>(
                    &sx[(cur ^ 1) * (TILE * XP) + rr[k] * XP + cc[k] * 4]) = pf[k];
        }
        if (ch + 2 < DIMX / CH) {             // prefetch chunk ch+2 from DRAM
            const float* xc = xb + (ch + 2) * CH;
#pragma unroll
            for (int k = 0; k < 4; ++k)
                pf[k] = *reinterpret_cast<const float4*>(xc + (size_t)rr[k] * DIMX + cc[k] * 4);
        }

        // Compute chunk ch: 8 groups x 4 dims; 2 x-LDS + 2 w-LDS per group.
        const float* x0p = sx + cur * (TILE * XP) + lane * XP;
        const float* x1p = x0p + 32 * XP;
        const float* wb  = wb0 + ch * (CH * 2);
#pragma unroll
        for (int g = 0; g < 8; ++g) {
            float4 x0 = *reinterpret_cast<const float4*>(x0p + g * 4);
            float4 x1 = *reinterpret_cast<const float4*>(x1p + g * 4);
            float4 wA = *reinterpret_cast<const float4*>(wb + g * 8);      // d0,d1
            float4 wB = *reinterpret_cast<const float4*>(wb + g * 8 + 4);  // d2,d3
            a00 = __fmaf_rn(x0.x, wA.x, a00);  a01 = __fmaf_rn(x0.x, wA.y, a01);
            a10 = __fmaf_rn(x1.x, wA.x, a10);  a11 = __fmaf_rn(x1.x, wA.y, a11);
            a00 = __fmaf_rn(x0.y, wA.z, a00);  a01 = __fmaf_rn(x0.y, wA.w, a01);
            a10 = __fmaf_rn(x1.y, wA.z, a10);  a11 = __fmaf_rn(x1.y, wA.w, a11);
            a00 = __fmaf_rn(x0.z, wB.x, a00);  a01 = __fmaf_rn(x0.z, wB.y, a01);
            a10 = __fmaf_rn(x1.z, wB.x, a10);  a11 = __fmaf_rn(x1.z, wB.y, a11);
            a00 = __fmaf_rn(x0.w, wB.z, a00);  a01 = __fmaf_rn(x0.w, wB.w, a01);
            a10 = __fmaf_rn(x1.w, wB.z, a10);  a11 = __fmaf_rn(x1.w, wB.w, a11);
        }
        __syncthreads();
    }

    // sigmoid (exp form, bit-matched) -> monotone descending key; emit 4.
    const int t0 = (int)rowBase + lane;
    const int t1 = t0 + 32;
    float acc[4] = {a00, a01, a10, a11};
    const int eid[4] = {e0, e1, e0, e1};
    const int tok[4] = {t0, t0, t1, t1};
#pragma unroll
    for (int u = 0; u < 4; ++u) {
        float em = __nv_expf(-acc[u]);
        float s  = __fdiv_rn(1.0f, __fadd_rn(1.0f, em));
        unsigned key = ~__float_as_uint(s);
        g_keys[eid[u] * T_TOKENS + tok[u]] = key;
        unsigned h = (unsigned)eid[u] * 16384u + (key >> 18);
        unsigned m = __match_any_sync(0xffffffffu, h);
        if ((int)lane == __ffs(m) - 1)
            atomicAdd(&g_hist[h], (unsigned)__popc(m));
    }
}

// ---------------------------------------------------------------------------
// Kernel 2: per-expert exact top-2048 (desc, ties -> lower index).
// (byte-identical to R10/R11's k2 — measured 27.6us)
// ---------------------------------------------------------------------------
#define K2_THREADS 1024
#define HC         4
#define MASK46     ((1ull << 46) - 1)

__global__ void __launch_bounds__(K2_THREADS) k2_topk(float* __restrict__ out, int writeIdx)
{
    extern __shared__ unsigned char sm2[];
    unsigned int*        hist  = reinterpret_cast<unsigned int*>(sm2);
    unsigned int*        hscan = reinterpret_cast<unsigned int*>(sm2 + 65536);
    unsigned long long*  sel   = reinterpret_cast<unsigned long long*>(sm2 + 81920);
    unsigned long long*  cand  = reinterpret_cast<unsigned long long*>(sm2 + 98304);

    __shared__ unsigned int s_wsum[32];
    __shared__ unsigned long long s_pref;
    __shared__ unsigned long long s_mask;
    __shared__ unsigned long long s_kstar;
    __shared__ int          s_want;
    __shared__ int          s_bin;
    __shared__ unsigned int s_before;
    __shared__ int          s_exact;
    __shared__ int          s_n;

    const int e    = blockIdx.x;
    const int tid  = threadIdx.x;
    const unsigned lane = tid & 31;
    const int wid  = tid >> 5;

    unsigned kreg[16];
    {
        const unsigned* gk = g_keys + e * T_TOKENS;
#pragma unroll
        for (int r = 0; r < 16; ++r)
            kreg[r] = gk[tid + r * K2_THREADS];
    }

    if (tid == 0) { s_exact = 0; s_n = 0; }
    __syncthreads();

    // ---- Level 0: scan global 14-bit histogram (16 bins/thread) ----
    {
        const uint4* gh = reinterpret_cast<const uint4*>(g_hist + e * 16384);
        unsigned lsum = 0;
        uint4 u0 = gh[tid * 4 + 0], u1 = gh[tid * 4 + 1];
        uint4 u2 = gh[tid * 4 + 2], u3 = gh[tid * 4 + 3];
        lsum = u0.x + u0.y + u0.z + u0.w + u1.x + u1.y + u1.z + u1.w
             + u2.x + u2.y + u2.z + u2.w + u3.x + u3.y + u3.z + u3.w;
        unsigned si = lsum;
#pragma unroll
        for (int o = 1; o < 32; o <<= 1) {
            unsigned n = __shfl_up_sync(0xffffffffu, si, o);
            if (lane >= (unsigned)o) si += n;
        }
        if (lane == 31) s_wsum[wid] = si;
        __syncthreads();
        if (wid == 0) {
            unsigned w = s_wsum[lane];
            unsigned wi = w;
#pragma unroll
            for (int o = 1; o < 32; o <<= 1) {
                unsigned n = __shfl_up_sync(0xffffffffu, wi, o);
                if (lane >= (unsigned)o) wi += n;
            }
            s_wsum[lane] = wi - w;
        }
        __syncthreads();
        unsigned base = s_wsum[wid] + (si - lsum);
        if ((int)base < KSEL && (int)(base + lsum) >= KSEL) {
            const unsigned* gb = g_hist + e * 16384 + tid * 16;
            unsigned run = base;
            for (int j = 0; j < 16; ++j) {
                unsigned c = gb[j];
                if ((int)run < KSEL && (int)(run + c) >= KSEL) {
                    s_bin = tid * 16 + j;
                    s_before = run;
                    if ((int)(run + c) == KSEL) s_exact = 1;
                    break;
                }
                run += c;
            }
        }
        __syncthreads();
        if (tid == 0) {
            s_want = KSEL - (int)s_before;
            s_pref = (unsigned long long)(unsigned)s_bin << 32;
            s_mask = 0x3FFFull << 32;
        }
        __syncthreads();
    }

    unsigned long long Kstar;
    if (s_exact) {
        Kstar = s_pref | 0xFFFFFFFFull;
    } else {
        const unsigned binv = (unsigned)s_bin;
#pragma unroll
        for (int r = 0; r < 16; ++r) {
            bool c = ((kreg[r] >> 18) == binv);
            unsigned bal = __ballot_sync(0xffffffffu, c);
            int base = 0;
            if (lane == 0 && bal) base = atomicAdd(&s_n, __popc(bal));
            base = __shfl_sync(0xffffffffu, base, 0);
            if (c) {
                int pos = base + __popc(bal & ((1u << lane) - 1u));
                if (pos < 2048)
                    cand[pos] = ((unsigned long long)kreg[r] << 14)
                              | (unsigned)(tid + r * K2_THREADS);
            }
        }
        __syncthreads();
        const int m = s_n;
        const int want = s_want;

        if (m <= 64) {
            if (wid == 0) {
                unsigned long long a = (lane < (unsigned)m) ? cand[lane] : ~0ull;
                unsigned long long b = (lane + 32 < (unsigned)m) ? cand[lane + 32] : ~0ull;
                const int g0 = (int)lane, g1 = (int)lane + 32;
                for (int k = 2; k <= 64; k <<= 1) {
                    for (int j = k >> 1; j >= 1; j >>= 1) {
                        if (j == 32) {
                            bool asc = ((g0 & k) == 0);
                            if ((a > b) == asc) { unsigned long long t = a; a = b; b = t; }
                        } else {
                            unsigned long long pa = __shfl_xor_sync(0xffffffffu, a, j);
                            unsigned long long pb = __shfl_xor_sync(0xffffffffu, b, j);
                            bool lower = ((lane & (unsigned)j) == 0u);
                            bool ascA  = ((g0 & k) == 0);
                            bool ascB  = ((g1 & k) == 0);
                            unsigned long long amin = (a < pa) ? a : pa;
                            unsigned long long amax = (a < pa) ? pa : a;
                            unsigned long long bmin = (b < pb) ? b : pb;
                            unsigned long long bmax = (b < pb) ? pb : b;
                            a = (lower == ascA) ? amin : amax;
                            b = (lower == ascB) ? bmin : bmax;
                        }
                    }
                }
                int idx = want - 1;
                unsigned long long va = __shfl_sync(0xffffffffu, a, idx & 31);
                unsigned long long vb = __shfl_sync(0xffffffffu, b, idx & 31);
                if (lane == 0) s_kstar = (idx < 32) ? va : vb;
            }
            __syncthreads();
            Kstar = s_kstar;
        } else {
            const int shifts[3] = {20, 10, 0};
            const int nbits [3] = {12, 10, 10};
            for (int lvl = 0; lvl < 3; ++lvl) {
                const int shift = shifts[lvl];
                const int nb    = 1 << nbits[lvl];
                const int wantLoc              = s_want;
                const unsigned long long mask  = s_mask;
                const unsigned long long pref  = s_pref;

                for (int i = tid; i < HC * 4096; i += K2_THREADS) hist[i] = 0u;
                __syncthreads();

                unsigned int* myhist = hist + (wid & (HC - 1)) * 4096;
#pragma unroll
                for (int r = 0; r < 16; ++r) {
                    unsigned long long K = ((unsigned long long)kreg[r] << 14)
                                         | (unsigned)(tid + r * K2_THREADS);
                    bool mm = ((K & mask) == pref);
                    unsigned active = __ballot_sync(0xffffffffu, mm);
                    if (mm) {
                        int bin = (int)((K >> shift) & (unsigned)(nb - 1));
                        unsigned same = __match_any_sync(active, bin);
                        if ((int)lane == (__ffs(same) - 1))
                            atomicAdd(&myhist[bin], (unsigned)__popc(same));
                    }
                }
                __syncthreads();
                {
                    unsigned v[4];
                    unsigned sthr = 0;
#pragma unroll
                    for (int j = 0; j < 4; ++j) {
                        int b = 4 * tid + j;
                        unsigned t = 0;
#pragma unroll
                        for (int c = 0; c < HC; ++c) t += hist[c * 4096 + b];
                        v[j] = t; sthr += t;
                    }
                    unsigned si = sthr;
#pragma unroll
                    for (int o = 1; o < 32; o <<= 1) {
                        unsigned n = __shfl_up_sync(0xffffffffu, si, o);
                        if (lane >= (unsigned)o) si += n;
                    }
                    if (lane == 31) s_wsum[wid] = si;
                    __syncthreads();
                    if (wid == 0) {
                        unsigned w = s_wsum[lane];
                        unsigned wi = w;
#pragma unroll
                        for (int o = 1; o < 32; o <<= 1) {
                            unsigned n = __shfl_up_sync(0xffffffffu, wi, o);
                            if (lane >= (unsigned)o) wi += n;
                        }
                        s_wsum[lane] = wi - w;
                    }
                    __syncthreads();
                    unsigned run = s_wsum[wid] + (si - sthr);
#pragma unroll
                    for (int j = 0; j < 4; ++j) {
                        run += v[j];
                        hscan[4 * tid + j] = run;
                    }
                }
                __syncthreads();
                for (int i = tid; i < nb; i += K2_THREADS) {
                    unsigned c = hscan[i];
                    unsigned p = (i > 0) ? hscan[i - 1] : 0u;
                    if ((int)c >= wantLoc && (int)p < wantLoc) {
                        s_bin = i; s_before = p;
                        if ((int)c == wantLoc) s_exact = 1;
                    }
                }
                __syncthreads();
                if (tid == 0) {
                    s_want = wantLoc - (int)s_before;
                    s_pref = pref | ((unsigned long long)(unsigned)s_bin << shift);
                    s_mask = mask | ((unsigned long long)(unsigned)(nb - 1) << shift);
                }
                __syncthreads();
                if (s_exact) break;
            }
            Kstar = s_pref | (~s_mask & MASK46);
        }
    }

    // ---- Final collect (atomic-free two-pass) ----
    {
        int cw = 0;
#pragma unroll
        for (int r = 0; r < 16; ++r) {
            unsigned long long K = ((unsigned long long)kreg[r] << 14)
                                 | (unsigned)(tid + r * K2_THREADS);
            unsigned bal = __ballot_sync(0xffffffffu, K <= Kstar);
            cw += __popc(bal);
        }
        if (lane == 0) s_wsum[wid] = (unsigned)cw;
        __syncthreads();
        if (wid == 0) {
            unsigned w = s_wsum[lane];
            unsigned wi = w;
#pragma unroll
            for (int o = 1; o < 32; o <<= 1) {
                unsigned n = __shfl_up_sync(0xffffffffu, wi, o);
                if (lane >= (unsigned)o) wi += n;
            }
            s_wsum[lane] = wi - w;
        }
        __syncthreads();
        int base = (int)s_wsum[wid];
#pragma unroll
        for (int r = 0; r < 16; ++r) {
            unsigned long long K = ((unsigned long long)kreg[r] << 14)
                                 | (unsigned)(tid + r * K2_THREADS);
            bool take = (K <= Kstar);
            unsigned bal = __ballot_sync(0xffffffffu, take);
            if (take) {
                int pos = base + __popc(bal & ((1u << lane) - 1u));
                sel[pos] = K;
            }
            base += __popc(bal);
        }
    }
    __syncthreads();

    // ---- Hybrid bitonic sort ascending over sel[2048] ----
    const int g0 = (wid << 6) | (int)lane;
    const int g1 = g0 + 32;
    unsigned long long a = sel[g0];
    unsigned long long b = sel[g1];

    for (int k = 2; k <= KSEL; k <<= 1) {
        int j = k >> 1;
        if (j >= 64) {
            sel[g0] = a; sel[g1] = b;
            __syncthreads();
            for (; j >= 64; j >>= 1) {
                int i = ((tid & ~(j - 1)) << 1) | (tid & (j - 1));
                int l = i | j;
                unsigned long long u = sel[i];
                unsigned long long v = sel[l];
                bool asc = ((i & k) == 0);
                if ((u > v) == asc) { sel[i] = v; sel[l] = u; }
                __syncthreads();
            }
            a = sel[g0]; b = sel[g1];
        }
        for (; j >= 1; j >>= 1) {
            if (j == 32) {
                bool asc = ((g0 & k) == 0);
                if ((a > b) == asc) { unsigned long long t = a; a = b; b = t; }
            } else {
                unsigned long long pa = __shfl_xor_sync(0xffffffffu, a, j);
                unsigned long long pb = __shfl_xor_sync(0xffffffffu, b, j);
                bool lower = ((lane & (unsigned)j) == 0u);
                bool ascA  = ((g0 & k) == 0);
                bool ascB  = ((g1 & k) == 0);
                unsigned long long amin = (a < pa) ? a : pa;
                unsigned long long amax = (a < pa) ? pa : a;
                unsigned long long bmin = (b < pb) ? b : pb;
                unsigned long long bmax = (b < pb) ? pb : b;
                a = (lower == ascA) ? amin : amax;
                b = (lower == ascB) ? bmin : bmax;
            }
        }
    }

    // Re-zero this expert's g_hist slice (restores invariant for replay).
    {
        uint4 z = make_uint4(0u, 0u, 0u, 0u);
        uint4* gz = reinterpret_cast<uint4*>(g_hist + e * 16384);
        for (int i = tid; i < 16384 / 4; i += K2_THREADS) gz[i] = z;
    }

    {
        float scA = __uint_as_float(~(unsigned)(a >> 14));
        float scB = __uint_as_float(~(unsigned)(b >> 14));
        out[e * KSEL + g0] = scA;
        out[e * KSEL + g1] = scB;
        if (writeIdx) {
            out[NE * KSEL + e * KSEL + g0] = (float)(unsigned)(a & 0x3FFFu);
            out[NE * KSEL + e * KSEL + g1] = (float)(unsigned)(b & 0x3FFFu);
        }
    }
}

// ---------------------------------------------------------------------------
extern "C" void kernel_launch(void* const* d_in, const int* in_sizes, int n_in,
                              void* d_out, int out_size)
{
    const float* x = (const float*)d_in[0];   // [16384, 2048] f32
    const float* W = (const float*)d_in[1];   // [8, 2048] f32
    float* out = (float*)d_out;

    const int SMEM1 = (4 * WPP + 2 * TILE * XP) * (int)sizeof(float); // 84032
    const int SMEM2 = 65536 + 16384 + 16384 + 16384;                  // 114688

    cudaFuncSetAttribute(k1_gemv, cudaFuncAttributeMaxDynamicSharedMemorySize, SMEM1);
    cudaFuncSetAttribute(k2_topk, cudaFuncAttributeMaxDynamicSharedMemorySize, SMEM2);

    const int writeIdx = (out_size >= 2 * NE * KSEL) ? 1 : 0;

    k1_gemv<<<T_TOKENS / TILE, K1T, SMEM1>>>(x, W);
    k2_topk<<<NE, K2_THREADS, SMEM2>>>(out, writeIdx);
}

// round 13
// speedup vs baseline: 4.3645x; 1.1523x over previous
#include <cuda_runtime.h>
#include <cstdint>

#define T_TOKENS 16384
#define DIMX     2048
#define NE       8
#define KSEL     2048

// libdevice exp — exact bits, immune to fast-math flags.
extern "C" __device__ float __nv_expf(float);

// cp.async primitives (LDGSTS.128)
#define CP_ASYNC16(dst_u32, src_ptr) \
    asm volatile("cp.async.cg.shared.global [%0], [%1], 16;" :: "r"(dst_u32), "l"(src_ptr))
#define CP_COMMIT() asm volatile("cp.async.commit_group;" ::: "memory")
#define CP_WAIT2()  asm volatile("cp.async.wait_group 2;" ::: "memory")

// Scratch: per-expert sort keys (key = ~bits(sigmoid(logit))) and a global
// 14-bit histogram of keys per expert (level 0 of the radix select).
// g_hist is zero at module load and re-zeroed by k2 every call (replay-safe).
__device__ unsigned int g_keys[NE * T_TOKENS];
__device__ unsigned int g_hist[NE * 16384];

// ---------------------------------------------------------------------------
// Kernel 1: logits + keys + global key-histogram.
// R12 structure (block = 64-token tile, warp P = expert pair, thread = 2
// tokens x 2 experts, bitwise-identical in-order fma.rn chains; W packed as
// expert-pair float4s -> 2 broadcast LDS.128 per 4-dim group).
// NEW: x staged via cp.async into a 4-stage ring -> prefetch distance 3
// chunks (~900 cyc) covers DRAM latency; no register staging, no STS stall.
// ---------------------------------------------------------------------------
#define K1T     128
#define TILE    64
#define CH      32
#define XP      36                // 144B x rows: 16B aligned, conflict-free
#define STGF    (TILE * XP)       // floats per ring stage (2304)
#define NSTG    4
#define WPP     4100              // per-pair pitch: 512 groups * 8 floats + 4

__global__ void __launch_bounds__(K1T) k1_gemv(const float* __restrict__ x,
                                               const float* __restrict__ W)
{
    extern __shared__ float sm[];
    float* swp = sm;                         // [4][WPP]  packed pairs, 65.6KB
    float* sx  = sm + 4 * WPP;               // [4][STGF] ring, 36.9KB

    const int tid  = threadIdx.x;
    const int lane = tid & 31;
    const int P    = tid >> 5;               // expert pair 0..3
    const int e0   = 2 * P, e1 = e0 + 1;
    const size_t rowBase = (size_t)blockIdx.x * TILE;

    // Stage W pair P: swp[P][d4*8 ..] = {e0 d0, e1 d0, e0 d1, e1 d1,
    //                                    e0 d2, e1 d2, e0 d3, e1 d3}
    {
        const float4* W0 = reinterpret_cast<const float4*>(W + e0 * DIMX);
        const float4* W1 = reinterpret_cast<const float4*>(W + e1 * DIMX);
        float* dst = swp + P * WPP;
#pragma unroll 4
        for (int it = 0; it < 16; ++it) {
            int d4 = it * 32 + lane;
            float4 w0 = W0[d4];
            float4 w1 = W1[d4];
            float4* dp = reinterpret_cast<float4*>(dst + d4 * 8);
            dp[0] = make_float4(w0.x, w1.x, w0.y, w1.y);
            dp[1] = make_float4(w0.z, w1.z, w0.w, w1.w);
        }
    }

    // x staging assignment: 64 rows x 8 float4-cols per 32-dim chunk; 4/thread.
    int rr[4], cc[4];
    unsigned sdst[4];
#pragma unroll
    for (int k = 0; k < 4; ++k) {
        int idx = tid + k * K1T;
        rr[k] = idx >> 3;
        cc[k] = idx & 7;
        sdst[k] = (unsigned)__cvta_generic_to_shared(&sx[rr[k] * XP + cc[k] * 4]);
    }

    const float* xb = x + rowBase * DIMX;

    // Prologue: issue chunks 0..2 into stages 0..2 (one commit group each).
#pragma unroll
    for (int s = 0; s < NSTG - 1; ++s) {
#pragma unroll
        for (int k = 0; k < 4; ++k)
            CP_ASYNC16(sdst[k] + s * (STGF * 4),
                       xb + (size_t)rr[k] * DIMX + s * CH + cc[k] * 4);
        CP_COMMIT();
    }

    float a00 = 0.0f, a01 = 0.0f, a10 = 0.0f, a11 = 0.0f;
    const float* wb0 = swp + P * WPP;

    for (int ch = 0; ch < DIMX / CH; ++ch) {
        CP_WAIT2();          // chunk ch's group retired (2 newer may pend)
        __syncthreads();     // publish to all warps (covers W on ch==0)

        // Issue chunk ch+3 into the stage vacated by chunk ch-1.
        if (ch + NSTG - 1 < DIMX / CH) {
            const int s = (ch + NSTG - 1) & (NSTG - 1);
#pragma unroll
            for (int k = 0; k < 4; ++k)
                CP_ASYNC16(sdst[k] + s * (STGF * 4),
                           xb + (size_t)rr[k] * DIMX + (ch + NSTG - 1) * CH + cc[k] * 4);
        }
        CP_COMMIT();         // always commit (empty groups keep wait arithmetic)

        // Compute chunk ch (identical FMA order to R12 — bitwise preserved).
        const float* x0p = sx + (ch & (NSTG - 1)) * STGF + lane * XP;
        const float* x1p = x0p + 32 * XP;
        const float* wb  = wb0 + ch * (CH * 2);
#pragma unroll
        for (int g = 0; g < 8; ++g) {
            float4 x0 = *reinterpret_cast<const float4*>(x0p + g * 4);
            float4 x1 = *reinterpret_cast<const float4*>(x1p + g * 4);
            float4 wA = *reinterpret_cast<const float4*>(wb + g * 8);      // d0,d1
            float4 wB = *reinterpret_cast<const float4*>(wb + g * 8 + 4);  // d2,d3
            a00 = __fmaf_rn(x0.x, wA.x, a00);  a01 = __fmaf_rn(x0.x, wA.y, a01);
            a10 = __fmaf_rn(x1.x, wA.x, a10);  a11 = __fmaf_rn(x1.x, wA.y, a11);
            a00 = __fmaf_rn(x0.y, wA.z, a00);  a01 = __fmaf_rn(x0.y, wA.w, a01);
            a10 = __fmaf_rn(x1.y, wA.z, a10);  a11 = __fmaf_rn(x1.y, wA.w, a11);
            a00 = __fmaf_rn(x0.z, wB.x, a00);  a01 = __fmaf_rn(x0.z, wB.y, a01);
            a10 = __fmaf_rn(x1.z, wB.x, a10);  a11 = __fmaf_rn(x1.z, wB.y, a11);
            a00 = __fmaf_rn(x0.w, wB.z, a00);  a01 = __fmaf_rn(x0.w, wB.w, a01);
            a10 = __fmaf_rn(x1.w, wB.z, a10);  a11 = __fmaf_rn(x1.w, wB.w, a11);
        }
        __syncthreads();     // all warps done with stage ch before it is reused
    }

    // sigmoid (exp form, bit-matched) -> monotone descending key; emit 4.
    const int t0 = (int)rowBase + lane;
    const int t1 = t0 + 32;
    float acc[4] = {a00, a01, a10, a11};
    const int eid[4] = {e0, e1, e0, e1};
    const int tok[4] = {t0, t0, t1, t1};
#pragma unroll
    for (int u = 0; u < 4; ++u) {
        float em = __nv_expf(-acc[u]);
        float s  = __fdiv_rn(1.0f, __fadd_rn(1.0f, em));
        unsigned key = ~__float_as_uint(s);
        g_keys[eid[u] * T_TOKENS + tok[u]] = key;
        unsigned h = (unsigned)eid[u] * 16384u + (key >> 18);
        unsigned m = __match_any_sync(0xffffffffu, h);
        if ((int)lane == __ffs(m) - 1)
            atomicAdd(&g_hist[h], (unsigned)__popc(m));
    }
}

// ---------------------------------------------------------------------------
// Kernel 2: per-expert exact top-2048 (desc, ties -> lower index).
// (byte-identical to R12's k2 — measured 27.7us)
// ---------------------------------------------------------------------------
#define K2_THREADS 1024
#define HC         4
#define MASK46     ((1ull << 46) - 1)

__global__ void __launch_bounds__(K2_THREADS) k2_topk(float* __restrict__ out, int writeIdx)
{
    extern __shared__ unsigned char sm2[];
    unsigned int*        hist  = reinterpret_cast<unsigned int*>(sm2);
    unsigned int*        hscan = reinterpret_cast<unsigned int*>(sm2 + 65536);
    unsigned long long*  sel   = reinterpret_cast<unsigned long long*>(sm2 + 81920);
    unsigned long long*  cand  = reinterpret_cast<unsigned long long*>(sm2 + 98304);

    __shared__ unsigned int s_wsum[32];
    __shared__ unsigned long long s_pref;
    __shared__ unsigned long long s_mask;
    __shared__ unsigned long long s_kstar;
    __shared__ int          s_want;
    __shared__ int          s_bin;
    __shared__ unsigned int s_before;
    __shared__ int          s_exact;
    __shared__ int          s_n;

    const int e    = blockIdx.x;
    const int tid  = threadIdx.x;
    const unsigned lane = tid & 31;
    const int wid  = tid >> 5;

    unsigned kreg[16];
    {
        const unsigned* gk = g_keys + e * T_TOKENS;
#pragma unroll
        for (int r = 0; r < 16; ++r)
            kreg[r] = gk[tid + r * K2_THREADS];
    }

    if (tid == 0) { s_exact = 0; s_n = 0; }
    __syncthreads();

    // ---- Level 0: scan global 14-bit histogram (16 bins/thread) ----
    {
        const uint4* gh = reinterpret_cast<const uint4*>(g_hist + e * 16384);
        unsigned lsum = 0;
        uint4 u0 = gh[tid * 4 + 0], u1 = gh[tid * 4 + 1];
        uint4 u2 = gh[tid * 4 + 2], u3 = gh[tid * 4 + 3];
        lsum = u0.x + u0.y + u0.z + u0.w + u1.x + u1.y + u1.z + u1.w
             + u2.x + u2.y + u2.z + u2.w + u3.x + u3.y + u3.z + u3.w;
        unsigned si = lsum;
#pragma unroll
        for (int o = 1; o < 32; o <<= 1) {
            unsigned n = __shfl_up_sync(0xffffffffu, si, o);
            if (lane >= (unsigned)o) si += n;
        }
        if (lane == 31) s_wsum[wid] = si;
        __syncthreads();
        if (wid == 0) {
            unsigned w = s_wsum[lane];
            unsigned wi = w;
#pragma unroll
            for (int o = 1; o < 32; o <<= 1) {
                unsigned n = __shfl_up_sync(0xffffffffu, wi, o);
                if (lane >= (unsigned)o) wi += n;
            }
            s_wsum[lane] = wi - w;
        }
        __syncthreads();
        unsigned base = s_wsum[wid] + (si - lsum);
        if ((int)base < KSEL && (int)(base + lsum) >= KSEL) {
            const unsigned* gb = g_hist + e * 16384 + tid * 16;
            unsigned run = base;
            for (int j = 0; j < 16; ++j) {
                unsigned c = gb[j];
                if ((int)run < KSEL && (int)(run + c) >= KSEL) {
                    s_bin = tid * 16 + j;
                    s_before = run;
                    if ((int)(run + c) == KSEL) s_exact = 1;
                    break;
                }
                run += c;
            }
        }
        __syncthreads();
        if (tid == 0) {
            s_want = KSEL - (int)s_before;
            s_pref = (unsigned long long)(unsigned)s_bin << 32;
            s_mask = 0x3FFFull << 32;
        }
        __syncthreads();
    }

    unsigned long long Kstar;
    if (s_exact) {
        Kstar = s_pref | 0xFFFFFFFFull;
    } else {
        const unsigned binv = (unsigned)s_bin;
#pragma unroll
        for (int r = 0; r < 16; ++r) {
            bool c = ((kreg[r] >> 18) == binv);
            unsigned bal = __ballot_sync(0xffffffffu, c);
            int base = 0;
            if (lane == 0 && bal) base = atomicAdd(&s_n, __popc(bal));
            base = __shfl_sync(0xffffffffu, base, 0);
            if (c) {
                int pos = base + __popc(bal & ((1u << lane) - 1u));
                if (pos < 2048)
                    cand[pos] = ((unsigned long long)kreg[r] << 14)
                              | (unsigned)(tid + r * K2_THREADS);
            }
        }
        __syncthreads();
        const int m = s_n;
        const int want = s_want;

        if (m <= 64) {
            if (wid == 0) {
                unsigned long long a = (lane < (unsigned)m) ? cand[lane] : ~0ull;
                unsigned long long b = (lane + 32 < (unsigned)m) ? cand[lane + 32] : ~0ull;
                const int g0 = (int)lane, g1 = (int)lane + 32;
                for (int k = 2; k <= 64; k <<= 1) {
                    for (int j = k >> 1; j >= 1; j >>= 1) {
                        if (j == 32) {
                            bool asc = ((g0 & k) == 0);
                            if ((a > b) == asc) { unsigned long long t = a; a = b; b = t; }
                        } else {
                            unsigned long long pa = __shfl_xor_sync(0xffffffffu, a, j);
                            unsigned long long pb = __shfl_xor_sync(0xffffffffu, b, j);
                            bool lower = ((lane & (unsigned)j) == 0u);
                            bool ascA  = ((g0 & k) == 0);
                            bool ascB  = ((g1 & k) == 0);
                            unsigned long long amin = (a < pa) ? a : pa;
                            unsigned long long amax = (a < pa) ? pa : a;
                            unsigned long long bmin = (b < pb) ? b : pb;
                            unsigned long long bmax = (b < pb) ? pb : b;
                            a = (lower == ascA) ? amin : amax;
                            b = (lower == ascB) ? bmin : bmax;
                        }
                    }
                }
                int idx = want - 1;
                unsigned long long va = __shfl_sync(0xffffffffu, a, idx & 31);
                unsigned long long vb = __shfl_sync(0xffffffffu, b, idx & 31);
                if (lane == 0) s_kstar = (idx < 32) ? va : vb;
            }
            __syncthreads();
            Kstar = s_kstar;
        } else {
            const int shifts[3] = {20, 10, 0};
            const int nbits [3] = {12, 10, 10};
            for (int lvl = 0; lvl < 3; ++lvl) {
                const int shift = shifts[lvl];
                const int nb    = 1 << nbits[lvl];
                const int wantLoc              = s_want;
                const unsigned long long mask  = s_mask;
                const unsigned long long pref  = s_pref;

                for (int i = tid; i < HC * 4096; i += K2_THREADS) hist[i] = 0u;
                __syncthreads();

                unsigned int* myhist = hist + (wid & (HC - 1)) * 4096;
#pragma unroll
                for (int r = 0; r < 16; ++r) {
                    unsigned long long K = ((unsigned long long)kreg[r] << 14)
                                         | (unsigned)(tid + r * K2_THREADS);
                    bool mm = ((K & mask) == pref);
                    unsigned active = __ballot_sync(0xffffffffu, mm);
                    if (mm) {
                        int bin = (int)((K >> shift) & (unsigned)(nb - 1));
                        unsigned same = __match_any_sync(active, bin);
                        if ((int)lane == (__ffs(same) - 1))
                            atomicAdd(&myhist[bin], (unsigned)__popc(same));
                    }
                }
                __syncthreads();
                {
                    unsigned v[4];
                    unsigned sthr = 0;
#pragma unroll
                    for (int j = 0; j < 4; ++j) {
                        int b = 4 * tid + j;
                        unsigned t = 0;
#pragma unroll
                        for (int c = 0; c < HC; ++c) t += hist[c * 4096 + b];
                        v[j] = t; sthr += t;
                    }
                    unsigned si = sthr;
#pragma unroll
                    for (int o = 1; o < 32; o <<= 1) {
                        unsigned n = __shfl_up_sync(0xffffffffu, si, o);
                        if (lane >= (unsigned)o) si += n;
                    }
                    if (lane == 31) s_wsum[wid] = si;
                    __syncthreads();
                    if (wid == 0) {
                        unsigned w = s_wsum[lane];
                        unsigned wi = w;
#pragma unroll
                        for (int o = 1; o < 32; o <<= 1) {
                            unsigned n = __shfl_up_sync(0xffffffffu, wi, o);
                            if (lane >= (unsigned)o) wi += n;
                        }
                        s_wsum[lane] = wi - w;
                    }
                    __syncthreads();
                    unsigned run = s_wsum[wid] + (si - sthr);
#pragma unroll
                    for (int j = 0; j < 4; ++j) {
                        run += v[j];
                        hscan[4 * tid + j] = run;
                    }
                }
                __syncthreads();
                for (int i = tid; i < nb; i += K2_THREADS) {
                    unsigned c = hscan[i];
                    unsigned p = (i > 0) ? hscan[i - 1] : 0u;
                    if ((int)c >= wantLoc && (int)p < wantLoc) {
                        s_bin = i; s_before = p;
                        if ((int)c == wantLoc) s_exact = 1;
                    }
                }
                __syncthreads();
                if (tid == 0) {
                    s_want = wantLoc - (int)s_before;
                    s_pref = pref | ((unsigned long long)(unsigned)s_bin << shift);
                    s_mask = mask | ((unsigned long long)(unsigned)(nb - 1) << shift);
                }
                __syncthreads();
                if (s_exact) break;
            }
            Kstar = s_pref | (~s_mask & MASK46);
        }
    }

    // ---- Final collect (atomic-free two-pass) ----
    {
        int cw = 0;
#pragma unroll
        for (int r = 0; r < 16; ++r) {
            unsigned long long K = ((unsigned long long)kreg[r] << 14)
                                 | (unsigned)(tid + r * K2_THREADS);
            unsigned bal = __ballot_sync(0xffffffffu, K <= Kstar);
            cw += __popc(bal);
        }
        if (lane == 0) s_wsum[wid] = (unsigned)cw;
        __syncthreads();
        if (wid == 0) {
            unsigned w = s_wsum[lane];
            unsigned wi = w;
#pragma unroll
            for (int o = 1; o < 32; o <<= 1) {
                unsigned n = __shfl_up_sync(0xffffffffu, wi, o);
                if (lane >= (unsigned)o) wi += n;
            }
            s_wsum[lane] = wi - w;
        }
        __syncthreads();
        int base = (int)s_wsum[wid];
#pragma unroll
        for (int r = 0; r < 16; ++r) {
            unsigned long long K = ((unsigned long long)kreg[r] << 14)
                                 | (unsigned)(tid + r * K2_THREADS);
            bool take = (K <= Kstar);
            unsigned bal = __ballot_sync(0xffffffffu, take);
            if (take) {
                int pos = base + __popc(bal & ((1u << lane) - 1u));
                sel[pos] = K;
            }
            base += __popc(bal);
        }
    }
    __syncthreads();

    // ---- Hybrid bitonic sort ascending over sel[2048] ----
    const int g0 = (wid << 6) | (int)lane;
    const int g1 = g0 + 32;
    unsigned long long a = sel[g0];
    unsigned long long b = sel[g1];

    for (int k = 2; k <= KSEL; k <<= 1) {
        int j = k >> 1;
        if (j >= 64) {
            sel[g0] = a; sel[g1] = b;
            __syncthreads();
            for (; j >= 64; j >>= 1) {
                int i = ((tid & ~(j - 1)) << 1) | (tid & (j - 1));
                int l = i | j;
                unsigned long long u = sel[i];
                unsigned long long v = sel[l];
                bool asc = ((i & k) == 0);
                if ((u > v) == asc) { sel[i] = v; sel[l] = u; }
                __syncthreads();
            }
            a = sel[g0]; b = sel[g1];
        }
        for (; j >= 1; j >>= 1) {
            if (j == 32) {
                bool asc = ((g0 & k) == 0);
                if ((a > b) == asc) { unsigned long long t = a; a = b; b = t; }
            } else {
                unsigned long long pa = __shfl_xor_sync(0xffffffffu, a, j);
                unsigned long long pb = __shfl_xor_sync(0xffffffffu, b, j);
                bool lower = ((lane & (unsigned)j) == 0u);
                bool ascA  = ((g0 & k) == 0);
                bool ascB  = ((g1 & k) == 0);
                unsigned long long amin = (a < pa) ? a : pa;
                unsigned long long amax = (a < pa) ? pa : a;
                unsigned long long bmin = (b < pb) ? b : pb;
                unsigned long long bmax = (b < pb) ? pb : b;
                a = (lower == ascA) ? amin : amax;
                b = (lower == ascB) ? bmin : bmax;
            }
        }
    }

    // Re-zero this expert's g_hist slice (restores invariant for replay).
    {
        uint4 z = make_uint4(0u, 0u, 0u, 0u);
        uint4* gz = reinterpret_cast<uint4*>(g_hist + e * 16384);
        for (int i = tid; i < 16384 / 4; i += K2_THREADS) gz[i] = z;
    }

    {
        float scA = __uint_as_float(~(unsigned)(a >> 14));
        float scB = __uint_as_float(~(unsigned)(b >> 14));
        out[e * KSEL + g0] = scA;
        out[e * KSEL + g1] = scB;
        if (writeIdx) {
            out[NE * KSEL + e * KSEL + g0] = (float)(unsigned)(a & 0x3FFFu);
            out[NE * KSEL + e * KSEL + g1] = (float)(unsigned)(b & 0x3FFFu);
        }
    }
}

// ---------------------------------------------------------------------------
extern "C" void kernel_launch(void* const* d_in, const int* in_sizes, int n_in,
                              void* d_out, int out_size)
{
    const float* x = (const float*)d_in[0];   // [16384, 2048] f32
    const float* W = (const float*)d_in[1];   // [8, 2048] f32
    float* out = (float*)d_out;

    const int SMEM1 = (4 * WPP + NSTG * STGF) * (int)sizeof(float);   // 102464
    const int SMEM2 = 65536 + 16384 + 16384 + 16384;                  // 114688

    cudaFuncSetAttribute(k1_gemv, cudaFuncAttributeMaxDynamicSharedMemorySize, SMEM1);
    cudaFuncSetAttribute(k2_topk, cudaFuncAttributeMaxDynamicSharedMemorySize, SMEM2);

    const int writeIdx = (out_size >= 2 * NE * KSEL) ? 1 : 0;

    k1_gemv<<<T_TOKENS / TILE, K1T, SMEM1>>>(x, W);
    k2_topk<<<NE, K2_THREADS, SMEM2>>>(out, writeIdx);
}

// round 14
// speedup vs baseline: 4.6544x; 1.0664x over previous
#include <cuda_runtime.h>
#include <cstdint>

#define T_TOKENS 16384
#define DIMX     2048
#define NE       8
#define KSEL     2048

// libdevice exp — exact bits, immune to fast-math flags.
extern "C" __device__ float __nv_expf(float);

// cp.async primitives (LDGSTS.128)
#define CP_ASYNC16(dst_u32, src_ptr) \
    asm volatile("cp.async.cg.shared.global [%0], [%1], 16;" :: "r"(dst_u32), "l"(src_ptr))
#define CP_COMMIT() asm volatile("cp.async.commit_group;" ::: "memory")
#define CP_WAIT2()  asm volatile("cp.async.wait_group 2;" ::: "memory")

// Scratch: per-expert sort keys (key = ~bits(sigmoid(logit))) and a global
// 14-bit histogram of keys per expert (level 0 of the radix select).
// g_hist is zero at module load and re-zeroed by k2 every call (replay-safe).
__device__ unsigned int g_keys[NE * T_TOKENS];
__device__ unsigned int g_hist[NE * 16384];

// ---------------------------------------------------------------------------
// Kernel 1: logits + keys + global key-histogram. (R13 structure; ONE
// barrier per chunk — the trailing sync was provably redundant: the issue in
// iter ch targets the stage holding chunk ch-1, which every warp finished
// computing before iter ch's top sync.)
// ---------------------------------------------------------------------------
#define K1T     128
#define TILE    64
#define CH      32
#define XP      36
#define STGF    (TILE * XP)
#define NSTG    4
#define WPP     4100

__global__ void __launch_bounds__(K1T) k1_gemv(const float* __restrict__ x,
                                               const float* __restrict__ W)
{
    extern __shared__ float sm[];
    float* swp = sm;                         // [4][WPP]  packed pairs, 65.6KB
    float* sx  = sm + 4 * WPP;               // [4][STGF] ring, 36.9KB

    const int tid  = threadIdx.x;
    const int lane = tid & 31;
    const int P    = tid >> 5;
    const int e0   = 2 * P, e1 = e0 + 1;
    const size_t rowBase = (size_t)blockIdx.x * TILE;

    {
        const float4* W0 = reinterpret_cast<const float4*>(W + e0 * DIMX);
        const float4* W1 = reinterpret_cast<const float4*>(W + e1 * DIMX);
        float* dst = swp + P * WPP;
#pragma unroll 4
        for (int it = 0; it < 16; ++it) {
            int d4 = it * 32 + lane;
            float4 w0 = W0[d4];
            float4 w1 = W1[d4];
            float4* dp = reinterpret_cast<float4*>(dst + d4 * 8);
            dp[0] = make_float4(w0.x, w1.x, w0.y, w1.y);
            dp[1] = make_float4(w0.z, w1.z, w0.w, w1.w);
        }
    }

    int rr[4], cc[4];
    unsigned sdst[4];
#pragma unroll
    for (int k = 0; k < 4; ++k) {
        int idx = tid + k * K1T;
        rr[k] = idx >> 3;
        cc[k] = idx & 7;
        sdst[k] = (unsigned)__cvta_generic_to_shared(&sx[rr[k] * XP + cc[k] * 4]);
    }

    const float* xb = x + rowBase * DIMX;

#pragma unroll
    for (int s = 0; s < NSTG - 1; ++s) {
#pragma unroll
        for (int k = 0; k < 4; ++k)
            CP_ASYNC16(sdst[k] + s * (STGF * 4),
                       xb + (size_t)rr[k] * DIMX + s * CH + cc[k] * 4);
        CP_COMMIT();
    }

    float a00 = 0.0f, a01 = 0.0f, a10 = 0.0f, a11 = 0.0f;
    const float* wb0 = swp + P * WPP;

    for (int ch = 0; ch < DIMX / CH; ++ch) {
        CP_WAIT2();          // chunk ch's group retired
        __syncthreads();     // publish; also fences reuse of stage (ch-1)&3

        if (ch + NSTG - 1 < DIMX / CH) {
            const int s = (ch + NSTG - 1) & (NSTG - 1);
#pragma unroll
            for (int k = 0; k < 4; ++k)
                CP_ASYNC16(sdst[k] + s * (STGF * 4),
                           xb + (size_t)rr[k] * DIMX + (ch + NSTG - 1) * CH + cc[k] * 4);
        }
        CP_COMMIT();

        const float* x0p = sx + (ch & (NSTG - 1)) * STGF + lane * XP;
        const float* x1p = x0p + 32 * XP;
        const float* wb  = wb0 + ch * (CH * 2);
#pragma unroll
        for (int g = 0; g < 8; ++g) {
            float4 x0 = *reinterpret_cast<const float4*>(x0p + g * 4);
            float4 x1 = *reinterpret_cast<const float4*>(x1p + g * 4);
            float4 wA = *reinterpret_cast<const float4*>(wb + g * 8);
            float4 wB = *reinterpret_cast<const float4*>(wb + g * 8 + 4);
            a00 = __fmaf_rn(x0.x, wA.x, a00);  a01 = __fmaf_rn(x0.x, wA.y, a01);
            a10 = __fmaf_rn(x1.x, wA.x, a10);  a11 = __fmaf_rn(x1.x, wA.y, a11);
            a00 = __fmaf_rn(x0.y, wA.z, a00);  a01 = __fmaf_rn(x0.y, wA.w, a01);
            a10 = __fmaf_rn(x1.y, wA.z, a10);  a11 = __fmaf_rn(x1.y, wA.w, a11);
            a00 = __fmaf_rn(x0.z, wB.x, a00);  a01 = __fmaf_rn(x0.z, wB.y, a01);
            a10 = __fmaf_rn(x1.z, wB.x, a10);  a11 = __fmaf_rn(x1.z, wB.y, a11);
            a00 = __fmaf_rn(x0.w, wB.z, a00);  a01 = __fmaf_rn(x0.w, wB.w, a01);
            a10 = __fmaf_rn(x1.w, wB.z, a10);  a11 = __fmaf_rn(x1.w, wB.w, a11);
        }
        // no trailing sync: next iter's top sync fences stage reuse
    }

    const int t0 = (int)rowBase + lane;
    const int t1 = t0 + 32;
    float acc[4] = {a00, a01, a10, a11};
    const int eid[4] = {e0, e1, e0, e1};
    const int tok[4] = {t0, t0, t1, t1};
#pragma unroll
    for (int u = 0; u < 4; ++u) {
        float em = __nv_expf(-acc[u]);
        float s  = __fdiv_rn(1.0f, __fadd_rn(1.0f, em));
        unsigned key = ~__float_as_uint(s);
        g_keys[eid[u] * T_TOKENS + tok[u]] = key;
        unsigned h = (unsigned)eid[u] * 16384u + (key >> 18);
        unsigned m = __match_any_sync(0xffffffffu, h);
        if ((int)lane == __ffs(m) - 1)
            atomicAdd(&g_hist[h], (unsigned)__popc(m));
    }
}

// ---------------------------------------------------------------------------
// Kernel 2: per-expert exact top-2048 (desc, ties -> lower index).
// Level 0 = global 14-bit histogram. Boundary-bin candidates resolved with
// ONE candidate-local 4096-bin level + warp sort (replaces the 3-level
// full-key radix, which is kept only as a gated rare path).
// ---------------------------------------------------------------------------
#define K2_THREADS 1024
#define HC         4
#define MASK46     ((1ull << 46) - 1)

__device__ __forceinline__ unsigned long long warp_sort64_pick(
    unsigned long long a, unsigned long long b, int idx, unsigned lane)
{
    const int g0 = (int)lane, g1 = (int)lane + 32;
    for (int k = 2; k <= 64; k <<= 1) {
        for (int j = k >> 1; j >= 1; j >>= 1) {
            if (j == 32) {
                bool asc = ((g0 & k) == 0);
                if ((a > b) == asc) { unsigned long long t = a; a = b; b = t; }
            } else {
                unsigned long long pa = __shfl_xor_sync(0xffffffffu, a, j);
                unsigned long long pb = __shfl_xor_sync(0xffffffffu, b, j);
                bool lower = ((lane & (unsigned)j) == 0u);
                bool ascA  = ((g0 & k) == 0);
                bool ascB  = ((g1 & k) == 0);
                unsigned long long amin = (a < pa) ? a : pa;
                unsigned long long amax = (a < pa) ? pa : a;
                unsigned long long bmin = (b < pb) ? b : pb;
                unsigned long long bmax = (b < pb) ? pb : b;
                a = (lower == ascA) ? amin : amax;
                b = (lower == ascB) ? bmin : bmax;
            }
        }
    }
    unsigned long long va = __shfl_sync(0xffffffffu, a, idx & 31);
    unsigned long long vb = __shfl_sync(0xffffffffu, b, idx & 31);
    return (idx < 32) ? va : vb;
}

__global__ void __launch_bounds__(K2_THREADS) k2_topk(float* __restrict__ out, int writeIdx)
{
    extern __shared__ unsigned char sm2[];
    unsigned int*        hist  = reinterpret_cast<unsigned int*>(sm2);             // 64KB
    unsigned int*        hscan = reinterpret_cast<unsigned int*>(sm2 + 65536);     // 16KB
    unsigned long long*  sel   = reinterpret_cast<unsigned long long*>(sm2 + 81920);  // 16KB
    unsigned long long*  cand  = reinterpret_cast<unsigned long long*>(sm2 + 98304);  // 16KB

    __shared__ unsigned int s_wsum[32];
    __shared__ unsigned long long s_pref;
    __shared__ unsigned long long s_mask;
    __shared__ unsigned long long s_kstar;
    __shared__ unsigned long long s_cand2[64];
    __shared__ int          s_want;
    __shared__ int          s_bin;
    __shared__ unsigned int s_before;
    __shared__ int          s_exact;
    __shared__ int          s_n;
    __shared__ int          s_bin2;
    __shared__ unsigned int s_before2;
    __shared__ int          s_exact2;
    __shared__ int          s_n2;

    const int e    = blockIdx.x;
    const int tid  = threadIdx.x;
    const unsigned lane = tid & 31;
    const int wid  = tid >> 5;

    unsigned kreg[16];
    {
        const unsigned* gk = g_keys + e * T_TOKENS;
#pragma unroll
        for (int r = 0; r < 16; ++r)
            kreg[r] = gk[tid + r * K2_THREADS];
    }

    if (tid == 0) { s_exact = 0; s_n = 0; s_exact2 = 0; s_n2 = 0; }
    __syncthreads();

    // ---- Level 0: scan global 14-bit histogram (16 bins/thread) ----
    {
        const uint4* gh = reinterpret_cast<const uint4*>(g_hist + e * 16384);
        unsigned lsum = 0;
        uint4 u0 = gh[tid * 4 + 0], u1 = gh[tid * 4 + 1];
        uint4 u2 = gh[tid * 4 + 2], u3 = gh[tid * 4 + 3];
        lsum = u0.x + u0.y + u0.z + u0.w + u1.x + u1.y + u1.z + u1.w
             + u2.x + u2.y + u2.z + u2.w + u3.x + u3.y + u3.z + u3.w;
        unsigned si = lsum;
#pragma unroll
        for (int o = 1; o < 32; o <<= 1) {
            unsigned n = __shfl_up_sync(0xffffffffu, si, o);
            if (lane >= (unsigned)o) si += n;
        }
        if (lane == 31) s_wsum[wid] = si;
        __syncthreads();
        if (wid == 0) {
            unsigned w = s_wsum[lane];
            unsigned wi = w;
#pragma unroll
            for (int o = 1; o < 32; o <<= 1) {
                unsigned n = __shfl_up_sync(0xffffffffu, wi, o);
                if (lane >= (unsigned)o) wi += n;
            }
            s_wsum[lane] = wi - w;
        }
        __syncthreads();
        unsigned base = s_wsum[wid] + (si - lsum);
        if ((int)base < KSEL && (int)(base + lsum) >= KSEL) {
            const unsigned* gb = g_hist + e * 16384 + tid * 16;
            unsigned run = base;
            for (int j = 0; j < 16; ++j) {
                unsigned c = gb[j];
                if ((int)run < KSEL && (int)(run + c) >= KSEL) {
                    s_bin = tid * 16 + j;
                    s_before = run;
                    if ((int)(run + c) == KSEL) s_exact = 1;
                    break;
                }
                run += c;
            }
        }
        __syncthreads();
        if (tid == 0) {
            s_want = KSEL - (int)s_before;
            s_pref = (unsigned long long)(unsigned)s_bin << 32;
            s_mask = 0x3FFFull << 32;
        }
        __syncthreads();
    }

    unsigned long long Kstar = 0ull;
    bool resolved = false;

    if (s_exact) {
        Kstar = s_pref | 0xFFFFFFFFull;
        resolved = true;
    } else {
        const unsigned binv = (unsigned)s_bin;
        const int want = s_want;

        // ---- Collect boundary-bin candidates (atomic-free two-pass) ----
        {
            int cw = 0;
#pragma unroll
            for (int r = 0; r < 16; ++r) {
                unsigned bal = __ballot_sync(0xffffffffu, (kreg[r] >> 18) == binv);
                cw += __popc(bal);
            }
            if (lane == 0) s_wsum[wid] = (unsigned)cw;
            __syncthreads();
            if (wid == 0) {
                unsigned w = s_wsum[lane];
                unsigned wi = w;
#pragma unroll
                for (int o = 1; o < 32; o <<= 1) {
                    unsigned n = __shfl_up_sync(0xffffffffu, wi, o);
                    if (lane >= (unsigned)o) wi += n;
                }
                s_wsum[lane] = wi - w;
                if (lane == 31) s_n = (int)wi;   // total m
            }
            __syncthreads();
            int base = (int)s_wsum[wid];
#pragma unroll
            for (int r = 0; r < 16; ++r) {
                bool c = ((kreg[r] >> 18) == binv);
                unsigned bal = __ballot_sync(0xffffffffu, c);
                if (c) {
                    int pos = base + __popc(bal & ((1u << lane) - 1u));
                    if (pos < 2048)
                        cand[pos] = ((unsigned long long)kreg[r] << 14)
                                  | (unsigned)(tid + r * K2_THREADS);
                }
                base += __popc(bal);
            }
        }
        __syncthreads();
        const int m = s_n;

        if (m <= 64) {
            if (wid == 0) {
                unsigned long long a = (lane < (unsigned)m) ? cand[lane] : ~0ull;
                unsigned long long b = (lane + 32 < (unsigned)m) ? cand[lane + 32] : ~0ull;
                unsigned long long ks = warp_sort64_pick(a, b, want - 1, lane);
                if (lane == 0) s_kstar = ks;
            }
            __syncthreads();
            Kstar = s_kstar;
            resolved = true;
        } else if (m <= 2048) {
            // ---- Candidate-local level: 4096 bins over K bits [20:32) ----
            for (int i = tid; i < 2 * 4096; i += K2_THREADS) hist[i] = 0u;
            __syncthreads();
#pragma unroll
            for (int q = 0; q < 2; ++q) {
                int j = tid + q * K2_THREADS;
                if (j < m) {
                    int bin = (int)((cand[j] >> 20) & 4095u);
                    atomicAdd(&hist[(wid & 1) * 4096 + bin], 1u);
                }
            }
            __syncthreads();
            {   // scan 4096 bins (sum 2 copies), 4/thread
                unsigned v[4];
                unsigned sthr = 0;
#pragma unroll
                for (int j = 0; j < 4; ++j) {
                    int b = 4 * tid + j;
                    v[j] = hist[b] + hist[4096 + b];
                    sthr += v[j];
                }
                unsigned si = sthr;
#pragma unroll
                for (int o = 1; o < 32; o <<= 1) {
                    unsigned n = __shfl_up_sync(0xffffffffu, si, o);
                    if (lane >= (unsigned)o) si += n;
                }
                if (lane == 31) s_wsum[wid] = si;
                __syncthreads();
                if (wid == 0) {
                    unsigned w = s_wsum[lane];
                    unsigned wi = w;
#pragma unroll
                    for (int o = 1; o < 32; o <<= 1) {
                        unsigned n = __shfl_up_sync(0xffffffffu, wi, o);
                        if (lane >= (unsigned)o) wi += n;
                    }
                    s_wsum[lane] = wi - w;
                }
                __syncthreads();
                unsigned run = s_wsum[wid] + (si - sthr);
#pragma unroll
                for (int j = 0; j < 4; ++j) {
                    unsigned p = run;
                    run += v[j];
                    if ((int)run >= want && (int)p < want) {
                        s_bin2 = 4 * tid + j;
                        s_before2 = p;
                        if ((int)run == want) s_exact2 = 1;
                    }
                }
            }
            __syncthreads();

            if (s_exact2) {
                Kstar = s_pref | ((unsigned long long)(unsigned)s_bin2 << 20)
                               | ((1ull << 20) - 1);
                resolved = true;
            } else {
                const unsigned b2 = (unsigned)s_bin2;
                const int want2 = want - (int)s_before2;
#pragma unroll
                for (int q = 0; q < 2; ++q) {
                    int j = tid + q * K2_THREADS;
                    if (j < m && (((cand[j] >> 20) & 4095u) == b2)) {
                        int pos = atomicAdd(&s_n2, 1);
                        if (pos < 64) s_cand2[pos] = cand[j];
                    }
                }
                __syncthreads();
                const int m2 = s_n2;
                if (m2 <= 64) {
                    if (wid == 0) {
                        unsigned long long a = (lane < (unsigned)m2) ? s_cand2[lane] : ~0ull;
                        unsigned long long b = (lane + 32 < (unsigned)m2) ? s_cand2[lane + 32] : ~0ull;
                        unsigned long long ks = warp_sort64_pick(a, b, want2 - 1, lane);
                        if (lane == 0) s_kstar = ks;
                    }
                    __syncthreads();
                    Kstar = s_kstar;
                    resolved = true;
                }
            }
        }

        if (!resolved) {
            // Rare path: 3-level full-key radix (handles m>2048 / tie storms).
            const int shifts[3] = {20, 10, 0};
            const int nbits [3] = {12, 10, 10};
            for (int lvl = 0; lvl < 3; ++lvl) {
                const int shift = shifts[lvl];
                const int nb    = 1 << nbits[lvl];
                const int wantLoc              = s_want;
                const unsigned long long mask  = s_mask;
                const unsigned long long pref  = s_pref;

                for (int i = tid; i < HC * 4096; i += K2_THREADS) hist[i] = 0u;
                if (tid == 0) s_exact = 0;
                __syncthreads();

                unsigned int* myhist = hist + (wid & (HC - 1)) * 4096;
#pragma unroll
                for (int r = 0; r < 16; ++r) {
                    unsigned long long K = ((unsigned long long)kreg[r] << 14)
                                         | (unsigned)(tid + r * K2_THREADS);
                    bool mm = ((K & mask) == pref);
                    unsigned active = __ballot_sync(0xffffffffu, mm);
                    if (mm) {
                        int bin = (int)((K >> shift) & (unsigned)(nb - 1));
                        unsigned same = __match_any_sync(active, bin);
                        if ((int)lane == (__ffs(same) - 1))
                            atomicAdd(&myhist[bin], (unsigned)__popc(same));
                    }
                }
                __syncthreads();
                {
                    unsigned v[4];
                    unsigned sthr = 0;
#pragma unroll
                    for (int j = 0; j < 4; ++j) {
                        int b = 4 * tid + j;
                        unsigned t = 0;
#pragma unroll
                        for (int c = 0; c < HC; ++c) t += hist[c * 4096 + b];
                        v[j] = t; sthr += t;
                    }
                    unsigned si = sthr;
#pragma unroll
                    for (int o = 1; o < 32; o <<= 1) {
                        unsigned n = __shfl_up_sync(0xffffffffu, si, o);
                        if (lane >= (unsigned)o) si += n;
                    }
                    if (lane == 31) s_wsum[wid] = si;
                    __syncthreads();
                    if (wid == 0) {
                        unsigned w = s_wsum[lane];
                        unsigned wi = w;
#pragma unroll
                        for (int o = 1; o < 32; o <<= 1) {
                            unsigned n = __shfl_up_sync(0xffffffffu, wi, o);
                            if (lane >= (unsigned)o) wi += n;
                        }
                        s_wsum[lane] = wi - w;
                    }
                    __syncthreads();
                    unsigned run = s_wsum[wid] + (si - sthr);
#pragma unroll
                    for (int j = 0; j < 4; ++j) {
                        run += v[j];
                        hscan[4 * tid + j] = run;
                    }
                }
                __syncthreads();
                for (int i = tid; i < nb; i += K2_THREADS) {
                    unsigned c = hscan[i];
                    unsigned p = (i > 0) ? hscan[i - 1] : 0u;
                    if ((int)c >= wantLoc && (int)p < wantLoc) {
                        s_bin = i; s_before = p;
                        if ((int)c == wantLoc) s_exact = 1;
                    }
                }
                __syncthreads();
                if (tid == 0) {
                    s_want = wantLoc - (int)s_before;
                    s_pref = pref | ((unsigned long long)(unsigned)s_bin << shift);
                    s_mask = mask | ((unsigned long long)(unsigned)(nb - 1) << shift);
                }
                __syncthreads();
                if (s_exact) break;
            }
            Kstar = s_pref | (~s_mask & MASK46);
        }
    }

    // ---- Final collect (atomic-free two-pass) ----
    {
        int cw = 0;
#pragma unroll
        for (int r = 0; r < 16; ++r) {
            unsigned long long K = ((unsigned long long)kreg[r] << 14)
                                 | (unsigned)(tid + r * K2_THREADS);
            unsigned bal = __ballot_sync(0xffffffffu, K <= Kstar);
            cw += __popc(bal);
        }
        if (lane == 0) s_wsum[wid] = (unsigned)cw;
        __syncthreads();
        if (wid == 0) {
            unsigned w = s_wsum[lane];
            unsigned wi = w;
#pragma unroll
            for (int o = 1; o < 32; o <<= 1) {
                unsigned n = __shfl_up_sync(0xffffffffu, wi, o);
                if (lane >= (unsigned)o) wi += n;
            }
            s_wsum[lane] = wi - w;
        }
        __syncthreads();
        int base = (int)s_wsum[wid];
#pragma unroll
        for (int r = 0; r < 16; ++r) {
            unsigned long long K = ((unsigned long long)kreg[r] << 14)
                                 | (unsigned)(tid + r * K2_THREADS);
            bool take = (K <= Kstar);
            unsigned bal = __ballot_sync(0xffffffffu, take);
            if (take) {
                int pos = base + __popc(bal & ((1u << lane) - 1u));
                sel[pos] = K;
            }
            base += __popc(bal);
        }
    }
    __syncthreads();

    // ---- Hybrid bitonic sort ascending over sel[2048] ----
    const int g0 = (wid << 6) | (int)lane;
    const int g1 = g0 + 32;
    unsigned long long a = sel[g0];
    unsigned long long b = sel[g1];

    for (int k = 2; k <= KSEL; k <<= 1) {
        int j = k >> 1;
        if (j >= 64) {
            sel[g0] = a; sel[g1] = b;
            __syncthreads();
            for (; j >= 64; j >>= 1) {
                int i = ((tid & ~(j - 1)) << 1) | (tid & (j - 1));
                int l = i | j;
                unsigned long long u = sel[i];
                unsigned long long v = sel[l];
                bool asc = ((i & k) == 0);
                if ((u > v) == asc) { sel[i] = v; sel[l] = u; }
                __syncthreads();
            }
            a = sel[g0]; b = sel[g1];
        }
        for (; j >= 1; j >>= 1) {
            if (j == 32) {
                bool asc = ((g0 & k) == 0);
                if ((a > b) == asc) { unsigned long long t = a; a = b; b = t; }
            } else {
                unsigned long long pa = __shfl_xor_sync(0xffffffffu, a, j);
                unsigned long long pb = __shfl_xor_sync(0xffffffffu, b, j);
                bool lower = ((lane & (unsigned)j) == 0u);
                bool ascA  = ((g0 & k) == 0);
                bool ascB  = ((g1 & k) == 0);
                unsigned long long amin = (a < pa) ? a : pa;
                unsigned long long amax = (a < pa) ? pa : a;
                unsigned long long bmin = (b < pb) ? b : pb;
                unsigned long long bmax = (b < pb) ? pb : b;
                a = (lower == ascA) ? amin : amax;
                b = (lower == ascB) ? bmin : bmax;
            }
        }
    }

    // Re-zero this expert's g_hist slice (restores invariant for replay).
    {
        uint4 z = make_uint4(0u, 0u, 0u, 0u);
        uint4* gz = reinterpret_cast<uint4*>(g_hist + e * 16384);
        for (int i = tid; i < 16384 / 4; i += K2_THREADS) gz[i] = z;
    }

    {
        float scA = __uint_as_float(~(unsigned)(a >> 14));
        float scB = __uint_as_float(~(unsigned)(b >> 14));
        out[e * KSEL + g0] = scA;
        out[e * KSEL + g1] = scB;
        if (writeIdx) {
            out[NE * KSEL + e * KSEL + g0] = (float)(unsigned)(a & 0x3FFFu);
            out[NE * KSEL + e * KSEL + g1] = (float)(unsigned)(b & 0x3FFFu);
        }
    }
}

// ---------------------------------------------------------------------------
extern "C" void kernel_launch(void* const* d_in, const int* in_sizes, int n_in,
                              void* d_out, int out_size)
{
    const float* x = (const float*)d_in[0];   // [16384, 2048] f32
    const float* W = (const float*)d_in[1];   // [8, 2048] f32
    float* out = (float*)d_out;

    const int SMEM1 = (4 * WPP + NSTG * STGF) * (int)sizeof(float);   // 102464
    const int SMEM2 = 65536 + 16384 + 16384 + 16384;                  // 114688

    cudaFuncSetAttribute(k1_gemv, cudaFuncAttributeMaxDynamicSharedMemorySize, SMEM1);
    cudaFuncSetAttribute(k2_topk, cudaFuncAttributeMaxDynamicSharedMemorySize, SMEM2);

    const int writeIdx = (out_size >= 2 * NE * KSEL) ? 1 : 0;

    k1_gemv<<<T_TOKENS / TILE, K1T, SMEM1>>>(x, W);
    k2_topk<<<NE, K2_THREADS, SMEM2>>>(out, writeIdx);
}